// round 5
// baseline (speedup 1.0000x reference)
#include <cuda_runtime.h>
#include <cuda_fp16.h>
#include <math.h>
#include <stdint.h>

#define BB 2
#define CC 256
#define NN 4096
#define KKEEP 409   // int(0.1 * 4096)

// Scratch in device globals (no runtime allocation allowed).
__device__ float   g_q[(size_t)BB*NN*CC];          // Q [b][n][c] fp32
__device__ float   g_k[(size_t)BB*NN*CC];          // K [b][n][c] fp32
__device__ __half2 g_vh[(size_t)BB*NN*(CC/2)];     // V [b][n][c/2] fp16x2
__device__ float   g_s[(size_t)BB*NN*NN];          // 134 MB score matrix

// ---------------------------------------------------------------------------
// Kernel 1: fused Q/K/V projection.  q/k fp32 [n][c], v fp16x2 [n][c/2]
// ---------------------------------------------------------------------------
__global__ __launch_bounds__(256) void proj_kernel(
    const float* __restrict__ x,
    const float* __restrict__ Wq, const float* __restrict__ bq,
    const float* __restrict__ Wk, const float* __restrict__ bk,
    const float* __restrict__ Wv, const float* __restrict__ bv)
{
    const int p = blockIdx.z % 3;
    const int b = blockIdx.z / 3;
    const float* W; const float* bias;
    if (p == 0)      { W = Wq; bias = bq; }
    else if (p == 1) { W = Wk; bias = bk; }
    else             { W = Wv; bias = bv; }
    const float* xb = x + (size_t)b * CC * NN;

    __shared__ float As[32][64];   // [c][n]
    __shared__ float Bs[32][65];   // [c][o]

    const int n0 = blockIdx.x * 64;
    const int o0 = blockIdx.y * 64;
    const int t  = threadIdx.x;
    const int tx = t & 15, ty = t >> 4;   // tx -> o, ty -> n

    float acc[4][4] = {};   // [n][o]
    for (int k0 = 0; k0 < CC; k0 += 32) {
        #pragma unroll
        for (int i = 0; i < 2; i++) {
            int idx = t + i*256;
            int cc = idx >> 4, f4 = idx & 15;
            float4 v4 = *(const float4*)(xb + (size_t)(k0+cc)*NN + n0 + f4*4);
            *(float4*)&As[cc][f4*4] = v4;
        }
        #pragma unroll
        for (int i = 0; i < 2; i++) {
            int idx = t + i*256;
            int oo = idx >> 3, f4 = idx & 7;
            float4 v4 = *(const float4*)(W + (size_t)(o0+oo)*CC + k0 + f4*4);
            Bs[f4*4+0][oo] = v4.x; Bs[f4*4+1][oo] = v4.y;
            Bs[f4*4+2][oo] = v4.z; Bs[f4*4+3][oo] = v4.w;
        }
        __syncthreads();
        #pragma unroll
        for (int kk = 0; kk < 32; kk++) {
            float a[4], bv2[4];
            #pragma unroll
            for (int i = 0; i < 4; i++) a[i]   = As[kk][ty*4+i];
            #pragma unroll
            for (int j = 0; j < 4; j++) bv2[j] = Bs[kk][tx*4+j];
            #pragma unroll
            for (int i = 0; i < 4; i++)
                #pragma unroll
                for (int j = 0; j < 4; j++)
                    acc[i][j] += a[i] * bv2[j];
        }
        __syncthreads();
    }
    if (p < 2) {
        float* out = (p == 0 ? g_q : g_k) + (size_t)b * NN * CC;
        #pragma unroll
        for (int i = 0; i < 4; i++) {
            int n = n0 + ty*4 + i;
            #pragma unroll
            for (int j = 0; j < 4; j++) {
                int o = o0 + tx*4 + j;
                out[(size_t)n*CC + o] = acc[i][j] + bias[o];
            }
        }
    } else {
        __half2* outv = g_vh + (size_t)b * NN * (CC/2);
        float b0 = bias[o0+tx*4+0], b1 = bias[o0+tx*4+1];
        float b2 = bias[o0+tx*4+2], b3 = bias[o0+tx*4+3];
        #pragma unroll
        for (int i = 0; i < 4; i++) {
            int n = n0 + ty*4 + i;
            size_t base = (size_t)n*(CC/2) + (o0 + tx*4)/2;
            outv[base]     = __floats2half2_rn(acc[i][0]+b0, acc[i][1]+b1);
            outv[base + 1] = __floats2half2_rn(acc[i][2]+b2, acc[i][3]+b3);
        }
    }
}

// ---------------------------------------------------------------------------
// Kernel 2: S = Q * K^T / 16 via mma.sync fp16 m16n8k16, 2-way-split 3-term:
//   x = b + s (b = fp16(x), s = fp16(x-b));  A*B ~= Ab*Bb + Ab*Bs + As*Bb
// CTA tile 128(i) x 128(j), 8 warps (32i x 64j each), K in 8 steps of 32
// (2 x k16 chunks). Double-buffered smem, 1 syncthreads per step.
//
// smem word layout per matrix per k16 chunk: 128 rows x 8 fp16x2 words.
// Pair layout: logical pair pr (0..3) holds (word pr, word pr+4) adjacent,
// with slot swizzle ((pr + (row>>2)) & 3) for conflict-free stores AND loads.
// ---------------------------------------------------------------------------
#define SC_KCW  1024                 // words per k16 chunk per matrix
#define SC_MATW 2048                 // words per matrix (2 chunks)
#define SC_BUFW (4*SC_MATW)          // A_big, A_small, B_big, B_small
#define SC_SMEM_BYTES (2*SC_BUFW*4)  // 65536

__device__ __forceinline__ uint32_t h2u(__half2 h) { return *reinterpret_cast<uint32_t*>(&h); }

__device__ __forceinline__ void split2(float x0, float x1, uint32_t& bw, uint32_t& sw) {
    __half b0 = __float2half_rn(x0), b1 = __float2half_rn(x1);
    float r0 = x0 - __half2float(b0), r1 = x1 - __half2float(b1);
    __half2 bb = __halves2half2(b0, b1);
    __half2 ss = __floats2half2_rn(r0, r1);
    bw = h2u(bb); sw = h2u(ss);
}

__device__ __forceinline__ void mma_f16(float* c, uint2 alo, uint2 ahi, uint2 b) {
    asm volatile(
        "mma.sync.aligned.m16n8k16.row.col.f32.f16.f16.f32 "
        "{%0,%1,%2,%3}, {%4,%5,%6,%7}, {%8,%9}, {%0,%1,%2,%3};"
        : "+f"(c[0]), "+f"(c[1]), "+f"(c[2]), "+f"(c[3])
        : "r"(alo.x), "r"(ahi.x), "r"(alo.y), "r"(ahi.y), "r"(b.x), "r"(b.y));
}

__device__ __forceinline__ int sw_off(int kc, int row, int pr) {
    return kc*SC_KCW + row*8 + (((pr) + (row >> 2)) & 3)*2;
}

__global__ __launch_bounds__(256, 1) void scores_mma_kernel()
{
    extern __shared__ uint32_t smw[];
    const int t    = threadIdx.x;
    const int lane = t & 31;
    const int wid  = t >> 5;
    const int b  = blockIdx.z;
    const int m0 = blockIdx.x * 128;   // j: K rows
    const int n0 = blockIdx.y * 128;   // i: Q rows
    const float* Q = g_q + (size_t)b*NN*CC;
    const float* K = g_k + (size_t)b*NN*CC;

    const int g  = lane >> 2;          // 0..7
    const int t4 = lane & 3;           // 0..3
    const int ib = (wid >> 1) * 32;    // warp i-offset
    const int jb = (wid & 1) * 64;     // warp j-offset

    // Producer: 1 thread per (matrix, row): mat 0 = Q->A, 1 = K->B
    const int mrow = t & 127;
    const int mat  = t >> 7;
    const float* src = mat ? (K + (size_t)(m0 + mrow)*CC)
                           : (Q + (size_t)(n0 + mrow)*CC);

    float4 xv[8];

    #define SC_LOAD(k0) do { \
        const float4* pp = (const float4*)(src + (k0)); \
        _Pragma("unroll") \
        for (int i = 0; i < 8; i++) xv[i] = pp[i]; \
    } while (0)

    #define SC_STORE(buf) do { \
        uint32_t* base = smw + (buf)*SC_BUFW + mat*2*SC_MATW; \
        const float* xf = (const float*)xv; \
        _Pragma("unroll") \
        for (int kc = 0; kc < 2; kc++) { \
            _Pragma("unroll") \
            for (int pr = 0; pr < 4; pr++) { \
                uint32_t b0w, s0w, b1w, s1w; \
                split2(xf[kc*16 + 2*pr],     xf[kc*16 + 2*pr + 1], b0w, s0w); \
                split2(xf[kc*16 + 2*pr + 8], xf[kc*16 + 2*pr + 9], b1w, s1w); \
                int o = sw_off(kc, mrow, pr); \
                *(uint2*)(base + o)           = make_uint2(b0w, b1w); \
                *(uint2*)(base + SC_MATW + o) = make_uint2(s0w, s1w); \
            } \
        } \
    } while (0)

    float acc[2][8][4];
    #pragma unroll
    for (int mt = 0; mt < 2; mt++)
        #pragma unroll
        for (int nt = 0; nt < 8; nt++)
            #pragma unroll
            for (int q = 0; q < 4; q++) acc[mt][nt][q] = 0.f;

    SC_LOAD(0);
    SC_STORE(0);

    for (int s = 0; s < 8; s++) {
        __syncthreads();
        if (s < 7) SC_LOAD((s+1)*32);

        const uint32_t* Abase = smw + (s & 1)*SC_BUFW;    // A_big; A_small +SC_MATW
        const uint32_t* Bbase = Abase + 2*SC_MATW;        // B_big; B_small +SC_MATW
        #pragma unroll
        for (int kc = 0; kc < 2; kc++) {
            uint2 ab[2][2], as_[2][2];
            #pragma unroll
            for (int mt = 0; mt < 2; mt++) {
                int ra = ib + mt*16 + g;
                int olo = sw_off(kc, ra, t4);
                int ohi = sw_off(kc, ra + 8, t4);
                ab[mt][0]  = *(const uint2*)(Abase + olo);
                ab[mt][1]  = *(const uint2*)(Abase + ohi);
                as_[mt][0] = *(const uint2*)(Abase + SC_MATW + olo);
                as_[mt][1] = *(const uint2*)(Abase + SC_MATW + ohi);
            }
            uint2 bbf[8], bsf[8];
            #pragma unroll
            for (int nt = 0; nt < 8; nt++) {
                int rn = jb + nt*8 + g;
                int o = sw_off(kc, rn, t4);
                bbf[nt] = *(const uint2*)(Bbase + o);
                bsf[nt] = *(const uint2*)(Bbase + SC_MATW + o);
            }
            #pragma unroll
            for (int mt = 0; mt < 2; mt++)
                #pragma unroll
                for (int nt = 0; nt < 8; nt++) {
                    mma_f16(acc[mt][nt], as_[mt][0], as_[mt][1], bbf[nt]);  // As*Bb
                    mma_f16(acc[mt][nt], ab[mt][0],  ab[mt][1],  bsf[nt]);  // Ab*Bs
                    mma_f16(acc[mt][nt], ab[mt][0],  ab[mt][1],  bbf[nt]);  // Ab*Bb
                }
        }
        if (s < 7) SC_STORE((s+1) & 1);
    }

    // Epilogue: scale + store.  c0:(g,2t4) c1:(g,2t4+1) c2:(g+8,2t4) c3:(g+8,2t4+1)
    float* S = g_s + (size_t)b*NN*NN;
    const float sc = 0.0625f;  // 1/sqrt(256)
    #pragma unroll
    for (int mt = 0; mt < 2; mt++) {
        #pragma unroll
        for (int nt = 0; nt < 8; nt++) {
            int rowi = n0 + ib + mt*16 + g;
            int colj = m0 + jb + nt*8 + 2*t4;
            float2 v0 = make_float2(acc[mt][nt][0]*sc, acc[mt][nt][1]*sc);
            float2 v1 = make_float2(acc[mt][nt][2]*sc, acc[mt][nt][3]*sc);
            *(float2*)(S + (size_t)rowi*NN + colj)     = v0;
            *(float2*)(S + (size_t)(rowi+8)*NN + colj) = v1;
        }
    }
}

// ---------------------------------------------------------------------------
// Kernel 3: per-row exact top-409 radix select + softmax + sparse AV (fp16 V).
// One block (256 threads) per (n, b).  AV: 64 channel-groups x 4-way row split.
// ---------------------------------------------------------------------------
__device__ __forceinline__ unsigned f2o(float f) {
    unsigned u = __float_as_uint(f);
    return u ^ ((unsigned)((int)u >> 31) | 0x80000000u);
}

__device__ __forceinline__ float2 u2f2(uint32_t u) {
    __half2 h = *reinterpret_cast<__half2*>(&u);
    return __half22float2(h);
}

__global__ __launch_bounds__(256) void topk_av_kernel(float* __restrict__ out)
{
    const int n = blockIdx.x;
    const int b = blockIdx.y;
    const int t = threadIdx.x;

    __shared__ __align__(16) float s_row[NN];   // 16 KB (reused for combine)
    __shared__ int   hist[256];
    __shared__ int   eqc[256];
    __shared__ int   mlist[KKEEP + 32];
    __shared__ float wlist[KKEEP + 32];
    __shared__ float red[256];
    __shared__ unsigned sh_prefix;
    __shared__ int sh_krem, sh_cnt;
    __shared__ float sh_max;

    const float* Srow = g_s + ((size_t)b*NN + n)*NN;

    float lmax = -INFINITY;
    for (int i = t; i < NN; i += 256) {
        float v = Srow[i];
        s_row[i] = v;
        lmax = fmaxf(lmax, v);
    }
    red[t] = lmax; __syncthreads();
    for (int s = 128; s > 0; s >>= 1) {
        if (t < s) red[t] = fmaxf(red[t], red[t+s]);
        __syncthreads();
    }
    if (t == 0) { sh_max = red[0]; sh_krem = KKEEP; sh_prefix = 0u; sh_cnt = 0; }
    __syncthreads();

    // Exact radix select: KKEEP-th largest key (4 x 8-bit passes, MSB first)
    for (int shift = 24; shift >= 0; shift -= 8) {
        hist[t] = 0; __syncthreads();
        unsigned pref = sh_prefix;
        for (int i = t; i < NN; i += 256) {
            unsigned u = f2o(s_row[i]);
            bool match = (shift == 24) || ((u >> (shift + 8)) == pref);
            if (match) atomicAdd(&hist[(u >> shift) & 255u], 1);
        }
        __syncthreads();
        if (t == 0) {
            int krem = sh_krem, cum = 0, d;
            for (d = 255; d >= 0; d--) {
                int c2 = hist[d];
                if (cum + c2 >= krem) break;
                cum += c2;
            }
            sh_krem = krem - cum;
            sh_prefix = (sh_prefix << 8) | (unsigned)d;
        }
        __syncthreads();
    }
    const unsigned uT  = sh_prefix;
    const int       rr = sh_krem;
    const float   smax = sh_max;

    // Count equals per blocked chunk [t*16, t*16+16) for index-ordered tie capping
    int cnteq = 0;
    {
        int base = t * 16;
        #pragma unroll
        for (int i = 0; i < 16; i++)
            if (f2o(s_row[base + i]) == uT) cnteq++;
    }
    eqc[t] = cnteq; __syncthreads();
    for (int off = 1; off < 256; off <<= 1) {
        int v = (t >= off) ? eqc[t - off] : 0;
        __syncthreads();
        eqc[t] += v;
        __syncthreads();
    }
    const int eqExcl = eqc[t] - cnteq;

    // Build (index, weight) list of exactly KKEEP selected elements
    {
        int base = t * 16;
        int local = 0;
        #pragma unroll
        for (int i = 0; i < 16; i++) {
            float s = s_row[base + i];
            unsigned u = f2o(s);
            bool sel = false;
            if (u > uT) sel = true;
            else if (u == uT) { if (eqExcl + local < rr) sel = true; local++; }
            if (sel) {
                int pos = atomicAdd(&sh_cnt, 1);
                mlist[pos] = base + i;
                wlist[pos] = __expf(s - smax);
            }
        }
    }
    __syncthreads();
    const int cnt = sh_cnt;           // == KKEEP

    // Z = sum of selected weights
    float z = 0.f;
    for (int i = t; i < cnt; i += 256) z += wlist[i];
    red[t] = z; __syncthreads();
    for (int s = 128; s > 0; s >>= 1) {
        if (t < s) red[t] += red[t+s];
        __syncthreads();
    }
    const float invZ = 1.0f / red[0];
    __syncthreads();   // s_row reuse below

    // Sparse AV: thread (q, c4): channel group c4 (4 channels, 8B), quarter q.
    const uint2* V2 = reinterpret_cast<const uint2*>(g_vh + (size_t)b*NN*(CC/2));
    const int c4 = t & 63;
    const int q  = t >> 6;
    float ax = 0.f, ay = 0.f, az = 0.f, aw = 0.f;
    int i = q;
    for (; i + 12 < cnt; i += 16) {
        float w0 = wlist[i],    w1 = wlist[i+4];
        float w2 = wlist[i+8],  w3 = wlist[i+12];
        int   r0 = mlist[i],    r1 = mlist[i+4];
        int   r2 = mlist[i+8],  r3 = mlist[i+12];
        uint2 u0 = V2[(size_t)r0*64 + c4];
        uint2 u1 = V2[(size_t)r1*64 + c4];
        uint2 u2 = V2[(size_t)r2*64 + c4];
        uint2 u3 = V2[(size_t)r3*64 + c4];
        float2 p; 
        p = u2f2(u0.x); ax += w0*p.x; ay += w0*p.y;
        p = u2f2(u0.y); az += w0*p.x; aw += w0*p.y;
        p = u2f2(u1.x); ax += w1*p.x; ay += w1*p.y;
        p = u2f2(u1.y); az += w1*p.x; aw += w1*p.y;
        p = u2f2(u2.x); ax += w2*p.x; ay += w2*p.y;
        p = u2f2(u2.y); az += w2*p.x; aw += w2*p.y;
        p = u2f2(u3.x); ax += w3*p.x; ay += w3*p.y;
        p = u2f2(u3.y); az += w3*p.x; aw += w3*p.y;
    }
    for (; i < cnt; i += 4) {
        float w = wlist[i];
        uint2 u = V2[(size_t)mlist[i]*64 + c4];
        float2 p;
        p = u2f2(u.x); ax += w*p.x; ay += w*p.y;
        p = u2f2(u.y); az += w*p.x; aw += w*p.y;
    }

    // Combine quarters 1..3 into quarter 0 via smem; write out[b][c][n].
    float4* comb = (float4*)s_row;
    if (q > 0) comb[(q-1)*64 + c4] = make_float4(ax, ay, az, aw);
    __syncthreads();
    if (q == 0) {
        #pragma unroll
        for (int j = 0; j < 3; j++) {
            float4 v = comb[j*64 + c4];
            ax += v.x; ay += v.y; az += v.z; aw += v.w;
        }
        size_t obase = ((size_t)b*CC + 4*c4)*NN + n;
        out[obase]        = ax * invZ;
        out[obase + NN]   = ay * invZ;
        out[obase + 2*NN] = az * invZ;
        out[obase + 3*NN] = aw * invZ;
    }
}

// ---------------------------------------------------------------------------
extern "C" void kernel_launch(void* const* d_in, const int* in_sizes, int n_in,
                              void* d_out, int out_size)
{
    const float* x  = (const float*)d_in[0];
    const float* Wq = (const float*)d_in[1];
    const float* bq = (const float*)d_in[2];
    const float* Wk = (const float*)d_in[3];
    const float* bk = (const float*)d_in[4];
    const float* Wv = (const float*)d_in[5];
    const float* bv = (const float*)d_in[6];
    float* out = (float*)d_out;

    cudaFuncSetAttribute(scores_mma_kernel,
                         cudaFuncAttributeMaxDynamicSharedMemorySize, SC_SMEM_BYTES);

    proj_kernel      <<<dim3(NN/64,  CC/64, BB*3), 256>>>(x, Wq, bq, Wk, bk, Wv, bv);
    scores_mma_kernel<<<dim3(NN/128, NN/128, BB),  256, SC_SMEM_BYTES>>>();
    topk_av_kernel   <<<dim3(NN, BB), 256>>>(out);
}

// round 8
// speedup vs baseline: 1.4993x; 1.4993x over previous
#include <cuda_runtime.h>
#include <cuda_fp16.h>
#include <math.h>
#include <stdint.h>

#define BB 2
#define CC 256
#define NN 4096
#define KKEEP 409   // int(0.1 * 4096)

// Scratch in device globals (no runtime allocation allowed).
__device__ float   g_q[(size_t)BB*NN*CC];          // Q [b][n][c] fp32
__device__ float   g_k[(size_t)BB*NN*CC];          // K [b][n][c] fp32
__device__ __half2 g_vh[(size_t)BB*NN*(CC/2)];     // V [b][n][c/2] fp16x2
__device__ float   g_s[(size_t)BB*NN*NN];          // 134 MB score matrix

// ---------------------------------------------------------------------------
// Kernel 1: fused Q/K/V projection.  q/k fp32 [n][c], v fp16x2 [n][c/2]
// (UNCHANGED from R4/R5 — serves as the ncu clock canary.)
// ---------------------------------------------------------------------------
__global__ __launch_bounds__(256) void proj_kernel(
    const float* __restrict__ x,
    const float* __restrict__ Wq, const float* __restrict__ bq,
    const float* __restrict__ Wk, const float* __restrict__ bk,
    const float* __restrict__ Wv, const float* __restrict__ bv)
{
    const int p = blockIdx.z % 3;
    const int b = blockIdx.z / 3;
    const float* W; const float* bias;
    if (p == 0)      { W = Wq; bias = bq; }
    else if (p == 1) { W = Wk; bias = bk; }
    else             { W = Wv; bias = bv; }
    const float* xb = x + (size_t)b * CC * NN;

    __shared__ float As[32][64];   // [c][n]
    __shared__ float Bs[32][65];   // [c][o]

    const int n0 = blockIdx.x * 64;
    const int o0 = blockIdx.y * 64;
    const int t  = threadIdx.x;
    const int tx = t & 15, ty = t >> 4;   // tx -> o, ty -> n

    float acc[4][4] = {};   // [n][o]
    for (int k0 = 0; k0 < CC; k0 += 32) {
        #pragma unroll
        for (int i = 0; i < 2; i++) {
            int idx = t + i*256;
            int cc = idx >> 4, f4 = idx & 15;
            float4 v4 = *(const float4*)(xb + (size_t)(k0+cc)*NN + n0 + f4*4);
            *(float4*)&As[cc][f4*4] = v4;
        }
        #pragma unroll
        for (int i = 0; i < 2; i++) {
            int idx = t + i*256;
            int oo = idx >> 3, f4 = idx & 7;
            float4 v4 = *(const float4*)(W + (size_t)(o0+oo)*CC + k0 + f4*4);
            Bs[f4*4+0][oo] = v4.x; Bs[f4*4+1][oo] = v4.y;
            Bs[f4*4+2][oo] = v4.z; Bs[f4*4+3][oo] = v4.w;
        }
        __syncthreads();
        #pragma unroll
        for (int kk = 0; kk < 32; kk++) {
            float a[4], bv2[4];
            #pragma unroll
            for (int i = 0; i < 4; i++) a[i]   = As[kk][ty*4+i];
            #pragma unroll
            for (int j = 0; j < 4; j++) bv2[j] = Bs[kk][tx*4+j];
            #pragma unroll
            for (int i = 0; i < 4; i++)
                #pragma unroll
                for (int j = 0; j < 4; j++)
                    acc[i][j] += a[i] * bv2[j];
        }
        __syncthreads();
    }
    if (p < 2) {
        float* out = (p == 0 ? g_q : g_k) + (size_t)b * NN * CC;
        #pragma unroll
        for (int i = 0; i < 4; i++) {
            int n = n0 + ty*4 + i;
            #pragma unroll
            for (int j = 0; j < 4; j++) {
                int o = o0 + tx*4 + j;
                out[(size_t)n*CC + o] = acc[i][j] + bias[o];
            }
        }
    } else {
        __half2* outv = g_vh + (size_t)b * NN * (CC/2);
        float b0 = bias[o0+tx*4+0], b1 = bias[o0+tx*4+1];
        float b2 = bias[o0+tx*4+2], b3 = bias[o0+tx*4+3];
        #pragma unroll
        for (int i = 0; i < 4; i++) {
            int n = n0 + ty*4 + i;
            size_t base = (size_t)n*(CC/2) + (o0 + tx*4)/2;
            outv[base]     = __floats2half2_rn(acc[i][0]+b0, acc[i][1]+b1);
            outv[base + 1] = __floats2half2_rn(acc[i][2]+b2, acc[i][3]+b3);
        }
    }
}

// ---------------------------------------------------------------------------
// Kernel 2: S = Q * K^T / 16 via mma.sync fp16 m16n8k16, 2-way-split 3-term:
//   x = b + s (b = fp16(x), s = fp16(x-b));  A*B ~= Ab*Bb + Ab*Bs + As*Bb
// (UNCHANGED from R5.)
// ---------------------------------------------------------------------------
#define SC_KCW  1024                 // words per k16 chunk per matrix
#define SC_MATW 2048                 // words per matrix (2 chunks)
#define SC_BUFW (4*SC_MATW)          // A_big, A_small, B_big, B_small
#define SC_SMEM_BYTES (2*SC_BUFW*4)  // 65536

__device__ __forceinline__ uint32_t h2u(__half2 h) { return *reinterpret_cast<uint32_t*>(&h); }

__device__ __forceinline__ void split2(float x0, float x1, uint32_t& bw, uint32_t& sw) {
    __half b0 = __float2half_rn(x0), b1 = __float2half_rn(x1);
    float r0 = x0 - __half2float(b0), r1 = x1 - __half2float(b1);
    __half2 bb = __halves2half2(b0, b1);
    __half2 ss = __floats2half2_rn(r0, r1);
    bw = h2u(bb); sw = h2u(ss);
}

__device__ __forceinline__ void mma_f16(float* c, uint2 alo, uint2 ahi, uint2 b) {
    asm volatile(
        "mma.sync.aligned.m16n8k16.row.col.f32.f16.f16.f32 "
        "{%0,%1,%2,%3}, {%4,%5,%6,%7}, {%8,%9}, {%0,%1,%2,%3};"
        : "+f"(c[0]), "+f"(c[1]), "+f"(c[2]), "+f"(c[3])
        : "r"(alo.x), "r"(ahi.x), "r"(alo.y), "r"(ahi.y), "r"(b.x), "r"(b.y));
}

__device__ __forceinline__ int sw_off(int kc, int row, int pr) {
    return kc*SC_KCW + row*8 + (((pr) + (row >> 2)) & 3)*2;
}

__global__ __launch_bounds__(256, 1) void scores_mma_kernel()
{
    extern __shared__ uint32_t smw[];
    const int t    = threadIdx.x;
    const int lane = t & 31;
    const int wid  = t >> 5;
    const int b  = blockIdx.z;
    const int m0 = blockIdx.x * 128;   // j: K rows
    const int n0 = blockIdx.y * 128;   // i: Q rows
    const float* Q = g_q + (size_t)b*NN*CC;
    const float* K = g_k + (size_t)b*NN*CC;

    const int g  = lane >> 2;          // 0..7
    const int t4 = lane & 3;           // 0..3
    const int ib = (wid >> 1) * 32;    // warp i-offset
    const int jb = (wid & 1) * 64;     // warp j-offset

    // Producer: 1 thread per (matrix, row): mat 0 = Q->A, 1 = K->B
    const int mrow = t & 127;
    const int mat  = t >> 7;
    const float* src = mat ? (K + (size_t)(m0 + mrow)*CC)
                           : (Q + (size_t)(n0 + mrow)*CC);

    float4 xv[8];

    #define SC_LOAD(k0) do { \
        const float4* pp = (const float4*)(src + (k0)); \
        _Pragma("unroll") \
        for (int i = 0; i < 8; i++) xv[i] = pp[i]; \
    } while (0)

    #define SC_STORE(buf) do { \
        uint32_t* base = smw + (buf)*SC_BUFW + mat*2*SC_MATW; \
        const float* xf = (const float*)xv; \
        _Pragma("unroll") \
        for (int kc = 0; kc < 2; kc++) { \
            _Pragma("unroll") \
            for (int pr = 0; pr < 4; pr++) { \
                uint32_t b0w, s0w, b1w, s1w; \
                split2(xf[kc*16 + 2*pr],     xf[kc*16 + 2*pr + 1], b0w, s0w); \
                split2(xf[kc*16 + 2*pr + 8], xf[kc*16 + 2*pr + 9], b1w, s1w); \
                int o = sw_off(kc, mrow, pr); \
                *(uint2*)(base + o)           = make_uint2(b0w, b1w); \
                *(uint2*)(base + SC_MATW + o) = make_uint2(s0w, s1w); \
            } \
        } \
    } while (0)

    float acc[2][8][4];
    #pragma unroll
    for (int mt = 0; mt < 2; mt++)
        #pragma unroll
        for (int nt = 0; nt < 8; nt++)
            #pragma unroll
            for (int q = 0; q < 4; q++) acc[mt][nt][q] = 0.f;

    SC_LOAD(0);
    SC_STORE(0);

    for (int s = 0; s < 8; s++) {
        __syncthreads();
        if (s < 7) SC_LOAD((s+1)*32);

        const uint32_t* Abase = smw + (s & 1)*SC_BUFW;    // A_big; A_small +SC_MATW
        const uint32_t* Bbase = Abase + 2*SC_MATW;        // B_big; B_small +SC_MATW
        #pragma unroll
        for (int kc = 0; kc < 2; kc++) {
            uint2 ab[2][2], as_[2][2];
            #pragma unroll
            for (int mt = 0; mt < 2; mt++) {
                int ra = ib + mt*16 + g;
                int olo = sw_off(kc, ra, t4);
                int ohi = sw_off(kc, ra + 8, t4);
                ab[mt][0]  = *(const uint2*)(Abase + olo);
                ab[mt][1]  = *(const uint2*)(Abase + ohi);
                as_[mt][0] = *(const uint2*)(Abase + SC_MATW + olo);
                as_[mt][1] = *(const uint2*)(Abase + SC_MATW + ohi);
            }
            uint2 bbf[8], bsf[8];
            #pragma unroll
            for (int nt = 0; nt < 8; nt++) {
                int rn = jb + nt*8 + g;
                int o = sw_off(kc, rn, t4);
                bbf[nt] = *(const uint2*)(Bbase + o);
                bsf[nt] = *(const uint2*)(Bbase + SC_MATW + o);
            }
            #pragma unroll
            for (int mt = 0; mt < 2; mt++)
                #pragma unroll
                for (int nt = 0; nt < 8; nt++) {
                    mma_f16(acc[mt][nt], as_[mt][0], as_[mt][1], bbf[nt]);  // As*Bb
                    mma_f16(acc[mt][nt], ab[mt][0],  ab[mt][1],  bsf[nt]);  // Ab*Bs
                    mma_f16(acc[mt][nt], ab[mt][0],  ab[mt][1],  bbf[nt]);  // Ab*Bb
                }
        }
        if (s < 7) SC_STORE((s+1) & 1);
    }

    // Epilogue: scale + store.
    float* S = g_s + (size_t)b*NN*NN;
    const float sc = 0.0625f;  // 1/sqrt(256)
    #pragma unroll
    for (int mt = 0; mt < 2; mt++) {
        #pragma unroll
        for (int nt = 0; nt < 8; nt++) {
            int rowi = n0 + ib + mt*16 + g;
            int colj = m0 + jb + nt*8 + 2*t4;
            float2 v0 = make_float2(acc[mt][nt][0]*sc, acc[mt][nt][1]*sc);
            float2 v1 = make_float2(acc[mt][nt][2]*sc, acc[mt][nt][3]*sc);
            *(float2*)(S + (size_t)rowi*NN + colj)     = v0;
            *(float2*)(S + (size_t)(rowi+8)*NN + colj) = v1;
        }
    }
}

// ---------------------------------------------------------------------------
// Kernel 3: per-row exact top-409 radix select + softmax + sparse AV (fp16 V).
// One block (256 threads) per (n, b).
// R6: warp-aggregated histogram atomics, shuffle scans/reductions,
//     ballot-compacted list build.
// ---------------------------------------------------------------------------
__device__ __forceinline__ unsigned f2o(float f) {
    unsigned u = __float_as_uint(f);
    return u ^ ((unsigned)((int)u >> 31) | 0x80000000u);
}

__device__ __forceinline__ float2 u2f2(uint32_t u) {
    __half2 h = *reinterpret_cast<__half2*>(&u);
    return __half22float2(h);
}

__global__ __launch_bounds__(256) void topk_av_kernel(float* __restrict__ out)
{
    const int n = blockIdx.x;
    const int b = blockIdx.y;
    const int t = threadIdx.x;
    const int lane = t & 31;
    const int wrp  = t >> 5;

    __shared__ __align__(16) float s_row[NN];   // 16 KB (reused for combine)
    __shared__ int   hist[256];
    __shared__ int   mlist[KKEEP + 32];
    __shared__ float wlist[KKEEP + 32];
    __shared__ float redf[8];
    __shared__ int   redi[8];
    __shared__ unsigned sh_prefix;
    __shared__ int sh_krem, sh_cnt;
    __shared__ float sh_max;

    const float* Srow = g_s + ((size_t)b*NN + n)*NN;

    // Load row + block max (shuffle reduction)
    float lmax = -INFINITY;
    for (int i = t; i < NN; i += 256) {
        float v = Srow[i];
        s_row[i] = v;
        lmax = fmaxf(lmax, v);
    }
    #pragma unroll
    for (int o = 16; o > 0; o >>= 1) lmax = fmaxf(lmax, __shfl_xor_sync(~0u, lmax, o));
    if (lane == 0) redf[wrp] = lmax;
    if (t == 0) { sh_krem = KKEEP; sh_prefix = 0u; sh_cnt = 0; }
    __syncthreads();
    if (t == 0) {
        float m = redf[0];
        #pragma unroll
        for (int w = 1; w < 8; w++) m = fmaxf(m, redf[w]);
        sh_max = m;
    }
    __syncthreads();
    const float smax = sh_max;

    // Exact radix select: KKEEP-th largest key (4 x 8-bit passes, MSB first).
    // Warp-aggregated histogram atomics (digits are heavily concentrated).
    for (int shift = 24; shift >= 0; shift -= 8) {
        hist[t] = 0; __syncthreads();
        unsigned pref = sh_prefix;
        #pragma unroll
        for (int it = 0; it < NN/256; it++) {
            int i = t + it*256;
            unsigned u = f2o(s_row[i]);
            bool match = (shift == 24) || ((u >> (shift + 8)) == pref);
            unsigned digit = (u >> shift) & 255u;
            unsigned bal = __ballot_sync(0xffffffffu, match);
            if (match) {
                unsigned peers = __match_any_sync(bal, digit);
                int leader = __ffs(peers) - 1;
                if (lane == leader) atomicAdd(&hist[digit], __popc(peers));
            }
        }
        __syncthreads();
        if (t == 0) {
            int krem = sh_krem, cum = 0, d;
            for (d = 255; d >= 0; d--) {
                int c2 = hist[d];
                if (cum + c2 >= krem) break;
                cum += c2;
            }
            sh_krem = krem - cum;
            sh_prefix = (sh_prefix << 8) | (unsigned)d;
        }
        __syncthreads();
    }
    const unsigned uT = sh_prefix;
    const int      rr = sh_krem;

    // Count equals per blocked chunk [t*16, t*16+16); exclusive scan via shuffles.
    int cnteq = 0;
    {
        int base = t * 16;
        #pragma unroll
        for (int i = 0; i < 16; i++)
            if (f2o(s_row[base + i]) == uT) cnteq++;
    }
    int inc = cnteq;
    #pragma unroll
    for (int o = 1; o < 32; o <<= 1) {
        int v = __shfl_up_sync(~0u, inc, o);
        if (lane >= o) inc += v;
    }
    if (lane == 31) redi[wrp] = inc;
    __syncthreads();
    int wpre = 0;
    #pragma unroll
    for (int w = 0; w < 8; w++) if (w < wrp) wpre += redi[w];
    const int eqExcl = wpre + inc - cnteq;

    // Build (index, weight) list; ballot-compacted (order irrelevant).
    {
        int base = t * 16;
        int local = 0;
        #pragma unroll
        for (int i = 0; i < 16; i++) {
            float s = s_row[base + i];
            unsigned u = f2o(s);
            bool sel = false;
            if (u > uT) sel = true;
            else if (u == uT) { if (eqExcl + local < rr) sel = true; local++; }
            unsigned m = __ballot_sync(0xffffffffu, sel);
            if (m) {
                int ldr = __ffs(m) - 1;
                int wbase = 0;
                if (lane == ldr) wbase = atomicAdd(&sh_cnt, __popc(m));
                wbase = __shfl_sync(0xffffffffu, wbase, ldr);
                if (sel) {
                    int pos = wbase + __popc(m & ((1u << lane) - 1u));
                    mlist[pos] = base + i;
                    wlist[pos] = __expf(s - smax);
                }
            }
        }
    }
    __syncthreads();
    const int cnt = sh_cnt;           // == KKEEP

    // Z = sum of selected weights (shuffle reduction)
    float z = 0.f;
    for (int i = t; i < cnt; i += 256) z += wlist[i];
    #pragma unroll
    for (int o = 16; o > 0; o >>= 1) z += __shfl_xor_sync(~0u, z, o);
    if (lane == 0) redf[wrp] = z;
    __syncthreads();
    float ztot = redf[0];
    #pragma unroll
    for (int w = 1; w < 8; w++) ztot += redf[w];
    const float invZ = 1.0f / ztot;
    __syncthreads();   // s_row reuse below

    // Sparse AV: thread (q, c4): channel group c4 (4 channels, 8B), quarter q.
    const uint2* V2 = reinterpret_cast<const uint2*>(g_vh + (size_t)b*NN*(CC/2));
    const int c4 = t & 63;
    const int q  = t >> 6;
    float ax = 0.f, ay = 0.f, az = 0.f, aw = 0.f;
    int i = q;
    for (; i + 12 < cnt; i += 16) {
        float w0 = wlist[i],    w1 = wlist[i+4];
        float w2 = wlist[i+8],  w3 = wlist[i+12];
        int   r0 = mlist[i],    r1 = mlist[i+4];
        int   r2 = mlist[i+8],  r3 = mlist[i+12];
        uint2 u0 = V2[(size_t)r0*64 + c4];
        uint2 u1 = V2[(size_t)r1*64 + c4];
        uint2 u2 = V2[(size_t)r2*64 + c4];
        uint2 u3 = V2[(size_t)r3*64 + c4];
        float2 p;
        p = u2f2(u0.x); ax += w0*p.x; ay += w0*p.y;
        p = u2f2(u0.y); az += w0*p.x; aw += w0*p.y;
        p = u2f2(u1.x); ax += w1*p.x; ay += w1*p.y;
        p = u2f2(u1.y); az += w1*p.x; aw += w1*p.y;
        p = u2f2(u2.x); ax += w2*p.x; ay += w2*p.y;
        p = u2f2(u2.y); az += w2*p.x; aw += w2*p.y;
        p = u2f2(u3.x); ax += w3*p.x; ay += w3*p.y;
        p = u2f2(u3.y); az += w3*p.x; aw += w3*p.y;
    }
    for (; i < cnt; i += 4) {
        float w = wlist[i];
        uint2 u = V2[(size_t)mlist[i]*64 + c4];
        float2 p;
        p = u2f2(u.x); ax += w*p.x; ay += w*p.y;
        p = u2f2(u.y); az += w*p.x; aw += w*p.y;
    }

    // Combine quarters 1..3 into quarter 0 via smem; write out[b][c][n].
    float4* comb = (float4*)s_row;
    if (q > 0) comb[(q-1)*64 + c4] = make_float4(ax, ay, az, aw);
    __syncthreads();
    if (q == 0) {
        #pragma unroll
        for (int j = 0; j < 3; j++) {
            float4 v = comb[j*64 + c4];
            ax += v.x; ay += v.y; az += v.z; aw += v.w;
        }
        size_t obase = ((size_t)b*CC + 4*c4)*NN + n;
        out[obase]        = ax * invZ;
        out[obase + NN]   = ay * invZ;
        out[obase + 2*NN] = az * invZ;
        out[obase + 3*NN] = aw * invZ;
    }
}

// ---------------------------------------------------------------------------
extern "C" void kernel_launch(void* const* d_in, const int* in_sizes, int n_in,
                              void* d_out, int out_size)
{
    const float* x  = (const float*)d_in[0];
    const float* Wq = (const float*)d_in[1];
    const float* bq = (const float*)d_in[2];
    const float* Wk = (const float*)d_in[3];
    const float* bk = (const float*)d_in[4];
    const float* Wv = (const float*)d_in[5];
    const float* bv = (const float*)d_in[6];
    float* out = (float*)d_out;

    cudaFuncSetAttribute(scores_mma_kernel,
                         cudaFuncAttributeMaxDynamicSharedMemorySize, SC_SMEM_BYTES);

    proj_kernel      <<<dim3(NN/64,  CC/64, BB*3), 256>>>(x, Wq, bq, Wk, bk, Wv, bv);
    scores_mma_kernel<<<dim3(NN/128, NN/128, BB),  256, SC_SMEM_BYTES>>>();
    topk_av_kernel   <<<dim3(NN, BB), 256>>>(out);
}

// round 11
// speedup vs baseline: 1.5167x; 1.0116x over previous
#include <cuda_runtime.h>
#include <cuda_fp16.h>
#include <math.h>
#include <stdint.h>

#define BB 2
#define CC 256
#define NN 4096
#define KKEEP 409   // int(0.1 * 4096)

// Scratch in device globals (no runtime allocation allowed).
__device__ __half  g_qb[(size_t)BB*NN*CC];         // Q big  (fp16)
__device__ __half  g_qs[(size_t)BB*NN*CC];         // Q small(fp16)
__device__ __half  g_kb[(size_t)BB*NN*CC];         // K big  (fp16)
__device__ __half  g_ks[(size_t)BB*NN*CC];         // K small(fp16)
__device__ __half2 g_vh[(size_t)BB*NN*(CC/2)];     // V [b][n][c/2] fp16x2
__device__ float   g_s[(size_t)BB*NN*NN];          // 134 MB score matrix (fp32)

// ---------------------------------------------------------------------------
// Kernel 1: fused Q/K/V projection.
// Q/K written pre-split as fp16 big+small; V as fp16x2.
// ---------------------------------------------------------------------------
__global__ __launch_bounds__(256) void proj_kernel(
    const float* __restrict__ x,
    const float* __restrict__ Wq, const float* __restrict__ bq,
    const float* __restrict__ Wk, const float* __restrict__ bk,
    const float* __restrict__ Wv, const float* __restrict__ bv)
{
    const int p = blockIdx.z % 3;
    const int b = blockIdx.z / 3;
    const float* W; const float* bias;
    if (p == 0)      { W = Wq; bias = bq; }
    else if (p == 1) { W = Wk; bias = bk; }
    else             { W = Wv; bias = bv; }
    const float* xb = x + (size_t)b * CC * NN;

    __shared__ float As[32][64];   // [c][n]
    __shared__ float Bs[32][65];   // [c][o]

    const int n0 = blockIdx.x * 64;
    const int o0 = blockIdx.y * 64;
    const int t  = threadIdx.x;
    const int tx = t & 15, ty = t >> 4;   // tx -> o, ty -> n

    float acc[4][4] = {};   // [n][o]
    for (int k0 = 0; k0 < CC; k0 += 32) {
        #pragma unroll
        for (int i = 0; i < 2; i++) {
            int idx = t + i*256;
            int cc = idx >> 4, f4 = idx & 15;
            float4 v4 = *(const float4*)(xb + (size_t)(k0+cc)*NN + n0 + f4*4);
            *(float4*)&As[cc][f4*4] = v4;
        }
        #pragma unroll
        for (int i = 0; i < 2; i++) {
            int idx = t + i*256;
            int oo = idx >> 3, f4 = idx & 7;
            float4 v4 = *(const float4*)(W + (size_t)(o0+oo)*CC + k0 + f4*4);
            Bs[f4*4+0][oo] = v4.x; Bs[f4*4+1][oo] = v4.y;
            Bs[f4*4+2][oo] = v4.z; Bs[f4*4+3][oo] = v4.w;
        }
        __syncthreads();
        #pragma unroll
        for (int kk = 0; kk < 32; kk++) {
            float a[4], bv2[4];
            #pragma unroll
            for (int i = 0; i < 4; i++) a[i]   = As[kk][ty*4+i];
            #pragma unroll
            for (int j = 0; j < 4; j++) bv2[j] = Bs[kk][tx*4+j];
            #pragma unroll
            for (int i = 0; i < 4; i++)
                #pragma unroll
                for (int j = 0; j < 4; j++)
                    acc[i][j] += a[i] * bv2[j];
        }
        __syncthreads();
    }
    float bb0 = bias[o0+tx*4+0], bb1 = bias[o0+tx*4+1];
    float bb2 = bias[o0+tx*4+2], bb3 = bias[o0+tx*4+3];
    if (p < 2) {
        __half2* outb = (__half2*)((p == 0 ? g_qb : g_kb) + (size_t)b * NN * CC);
        __half2* outs = (__half2*)((p == 0 ? g_qs : g_ks) + (size_t)b * NN * CC);
        #pragma unroll
        for (int i = 0; i < 4; i++) {
            int n = n0 + ty*4 + i;
            float v0 = acc[i][0]+bb0, v1 = acc[i][1]+bb1;
            float v2 = acc[i][2]+bb2, v3 = acc[i][3]+bb3;
            __half h0 = __float2half_rn(v0), h1 = __float2half_rn(v1);
            __half h2 = __float2half_rn(v2), h3 = __float2half_rn(v3);
            size_t base = (size_t)n*(CC/2) + (o0 + tx*4)/2;
            outb[base]     = __halves2half2(h0, h1);
            outb[base + 1] = __halves2half2(h2, h3);
            outs[base]     = __floats2half2_rn(v0 - __half2float(h0), v1 - __half2float(h1));
            outs[base + 1] = __floats2half2_rn(v2 - __half2float(h2), v3 - __half2float(h3));
        }
    } else {
        __half2* outv = g_vh + (size_t)b * NN * (CC/2);
        #pragma unroll
        for (int i = 0; i < 4; i++) {
            int n = n0 + ty*4 + i;
            size_t base = (size_t)n*(CC/2) + (o0 + tx*4)/2;
            outv[base]     = __floats2half2_rn(acc[i][0]+bb0, acc[i][1]+bb1);
            outv[base + 1] = __floats2half2_rn(acc[i][2]+bb2, acc[i][3]+bb3);
        }
    }
}

// ---------------------------------------------------------------------------
// Kernel 2: S = Q * K^T / 16 via mma.sync fp16 m16n8k16, 3-term compensated
// (split precomputed by proj). Producer is pure load/repack/store.
// ---------------------------------------------------------------------------
#define SC_KCW  1024                 // words per k16 chunk per matrix
#define SC_MATW 2048                 // words per matrix (2 chunks)
#define SC_BUFW (4*SC_MATW)          // A_big, A_small, B_big, B_small
#define SC_SMEM_BYTES (2*SC_BUFW*4)  // 65536

__device__ __forceinline__ void mma_f16(float* c, uint2 alo, uint2 ahi, uint2 b) {
    asm volatile(
        "mma.sync.aligned.m16n8k16.row.col.f32.f16.f16.f32 "
        "{%0,%1,%2,%3}, {%4,%5,%6,%7}, {%8,%9}, {%0,%1,%2,%3};"
        : "+f"(c[0]), "+f"(c[1]), "+f"(c[2]), "+f"(c[3])
        : "r"(alo.x), "r"(ahi.x), "r"(alo.y), "r"(ahi.y), "r"(b.x), "r"(b.y));
}

__device__ __forceinline__ int sw_off(int kc, int row, int pr) {
    return kc*SC_KCW + row*8 + (((pr) + (row >> 2)) & 3)*2;
}

__global__ __launch_bounds__(256, 1) void scores_mma_kernel()
{
    extern __shared__ uint32_t smw[];
    const int t    = threadIdx.x;
    const int lane = t & 31;
    const int wid  = t >> 5;
    const int b  = blockIdx.z;
    const int m0 = blockIdx.x * 128;   // j: K rows
    const int n0 = blockIdx.y * 128;   // i: Q rows

    const int g  = lane >> 2;          // 0..7
    const int t4 = lane & 3;           // 0..3
    const int ib = (wid >> 1) * 32;    // warp i-offset
    const int jb = (wid & 1) * 64;     // warp j-offset

    // Producer: 1 thread per (matrix, row): mat 0 = Q->A, 1 = K->B
    const int mrow = t & 127;
    const int mat  = t >> 7;
    const __half* srcb = mat ? (g_kb + (size_t)(b*NN + m0 + mrow)*CC)
                             : (g_qb + (size_t)(b*NN + n0 + mrow)*CC);
    const __half* srcs = mat ? (g_ks + (size_t)(b*NN + m0 + mrow)*CC)
                             : (g_qs + (size_t)(b*NN + n0 + mrow)*CC);

    uint4 bigv[2], smlv[2];   // 16 words total per K-step (32 halves)... per half-step

    // 32 halves per step = 16 words = 4 uint4 per array; stage in two halves to
    // keep register pressure down: use arrays of 4.
    uint4 bigv4[4], smlv4[4];

    #define SC_LOAD(k0) do { \
        const uint4* pb = (const uint4*)(srcb + (k0)); \
        const uint4* ps = (const uint4*)(srcs + (k0)); \
        _Pragma("unroll") \
        for (int i = 0; i < 4; i++) { bigv4[i] = pb[i]; smlv4[i] = ps[i]; } \
    } while (0)

    #define SC_STORE(buf) do { \
        uint32_t* base = smw + (buf)*SC_BUFW + mat*2*SC_MATW; \
        const uint32_t* wb = (const uint32_t*)bigv4; \
        const uint32_t* ws = (const uint32_t*)smlv4; \
        _Pragma("unroll") \
        for (int kc = 0; kc < 2; kc++) { \
            _Pragma("unroll") \
            for (int pr = 0; pr < 4; pr++) { \
                int o = sw_off(kc, mrow, pr); \
                *(uint2*)(base + o)           = make_uint2(wb[kc*8+pr], wb[kc*8+pr+4]); \
                *(uint2*)(base + SC_MATW + o) = make_uint2(ws[kc*8+pr], ws[kc*8+pr+4]); \
            } \
        } \
    } while (0)

    float acc[2][8][4];
    #pragma unroll
    for (int mt = 0; mt < 2; mt++)
        #pragma unroll
        for (int nt = 0; nt < 8; nt++)
            #pragma unroll
            for (int q = 0; q < 4; q++) acc[mt][nt][q] = 0.f;

    SC_LOAD(0);
    SC_STORE(0);

    for (int s = 0; s < 8; s++) {
        __syncthreads();
        if (s < 7) SC_LOAD((s+1)*32);

        const uint32_t* Abase = smw + (s & 1)*SC_BUFW;    // A_big; A_small +SC_MATW
        const uint32_t* Bbase = Abase + 2*SC_MATW;        // B_big; B_small +SC_MATW
        #pragma unroll
        for (int kc = 0; kc < 2; kc++) {
            uint2 ab[2][2], as_[2][2];
            #pragma unroll
            for (int mt = 0; mt < 2; mt++) {
                int ra = ib + mt*16 + g;
                int olo = sw_off(kc, ra, t4);
                int ohi = sw_off(kc, ra + 8, t4);
                ab[mt][0]  = *(const uint2*)(Abase + olo);
                ab[mt][1]  = *(const uint2*)(Abase + ohi);
                as_[mt][0] = *(const uint2*)(Abase + SC_MATW + olo);
                as_[mt][1] = *(const uint2*)(Abase + SC_MATW + ohi);
            }
            uint2 bbf[8], bsf[8];
            #pragma unroll
            for (int nt = 0; nt < 8; nt++) {
                int rn = jb + nt*8 + g;
                int o = sw_off(kc, rn, t4);
                bbf[nt] = *(const uint2*)(Bbase + o);
                bsf[nt] = *(const uint2*)(Bbase + SC_MATW + o);
            }
            #pragma unroll
            for (int mt = 0; mt < 2; mt++)
                #pragma unroll
                for (int nt = 0; nt < 8; nt++) {
                    mma_f16(acc[mt][nt], as_[mt][0], as_[mt][1], bbf[nt]);  // As*Bb
                    mma_f16(acc[mt][nt], ab[mt][0],  ab[mt][1],  bsf[nt]);  // Ab*Bs
                    mma_f16(acc[mt][nt], ab[mt][0],  ab[mt][1],  bbf[nt]);  // Ab*Bb
                }
        }
        if (s < 7) SC_STORE((s+1) & 1);
    }

    // Epilogue: scale + fp32 store.
    float* S = g_s + (size_t)b*NN*NN;
    const float sc = 0.0625f;  // 1/sqrt(256)
    #pragma unroll
    for (int mt = 0; mt < 2; mt++) {
        #pragma unroll
        for (int nt = 0; nt < 8; nt++) {
            int rowi = n0 + ib + mt*16 + g;
            int colj = m0 + jb + nt*8 + 2*t4;
            float2 v0 = make_float2(acc[mt][nt][0]*sc, acc[mt][nt][1]*sc);
            float2 v1 = make_float2(acc[mt][nt][2]*sc, acc[mt][nt][3]*sc);
            *(float2*)(S + (size_t)rowi*NN + colj)     = v0;
            *(float2*)(S + (size_t)(rowi+8)*NN + colj) = v1;
        }
    }
}

// ---------------------------------------------------------------------------
// Kernel 3: per-row exact top-409 radix select on fp32 keys + softmax +
// sparse AV (fp16 V).  One block (256 threads) per (n, b).  (R8 version.)
// ---------------------------------------------------------------------------
__device__ __forceinline__ unsigned f2o(float f) {
    unsigned u = __float_as_uint(f);
    return u ^ ((unsigned)((int)u >> 31) | 0x80000000u);
}

__device__ __forceinline__ float2 u2f2(uint32_t u) {
    __half2 h = *reinterpret_cast<__half2*>(&u);
    return __half22float2(h);
}

__global__ __launch_bounds__(256) void topk_av_kernel(float* __restrict__ out)
{
    const int n = blockIdx.x;
    const int b = blockIdx.y;
    const int t = threadIdx.x;
    const int lane = t & 31;
    const int wrp  = t >> 5;

    __shared__ __align__(16) float s_row[NN];   // 16 KB (reused for combine)
    __shared__ int   hist[256];
    __shared__ int   mlist[KKEEP + 32];
    __shared__ float wlist[KKEEP + 32];
    __shared__ float redf[8];
    __shared__ int   redi[8];
    __shared__ unsigned sh_prefix;
    __shared__ int sh_krem, sh_cnt;
    __shared__ float sh_max;

    const float* Srow = g_s + ((size_t)b*NN + n)*NN;

    // Load row + block max (shuffle reduction)
    float lmax = -INFINITY;
    for (int i = t; i < NN; i += 256) {
        float v = Srow[i];
        s_row[i] = v;
        lmax = fmaxf(lmax, v);
    }
    #pragma unroll
    for (int o = 16; o > 0; o >>= 1) lmax = fmaxf(lmax, __shfl_xor_sync(~0u, lmax, o));
    if (lane == 0) redf[wrp] = lmax;
    if (t == 0) { sh_krem = KKEEP; sh_prefix = 0u; sh_cnt = 0; }
    __syncthreads();
    if (t == 0) {
        float m = redf[0];
        #pragma unroll
        for (int w = 1; w < 8; w++) m = fmaxf(m, redf[w]);
        sh_max = m;
    }
    __syncthreads();
    const float smax = sh_max;

    // Exact radix select: 4 x 8-bit passes, MSB first, warp-aggregated atomics.
    for (int shift = 24; shift >= 0; shift -= 8) {
        hist[t] = 0; __syncthreads();
        unsigned pref = sh_prefix;
        #pragma unroll
        for (int it = 0; it < NN/256; it++) {
            int i = t + it*256;
            unsigned u = f2o(s_row[i]);
            bool match = (shift == 24) || ((u >> (shift + 8)) == pref);
            unsigned digit = (u >> shift) & 255u;
            unsigned bal = __ballot_sync(0xffffffffu, match);
            if (match) {
                unsigned peers = __match_any_sync(bal, digit);
                int leader = __ffs(peers) - 1;
                if (lane == leader) atomicAdd(&hist[digit], __popc(peers));
            }
        }
        __syncthreads();
        if (t == 0) {
            int krem = sh_krem, cum = 0, d;
            for (d = 255; d >= 0; d--) {
                int c2 = hist[d];
                if (cum + c2 >= krem) break;
                cum += c2;
            }
            sh_krem = krem - cum;
            sh_prefix = (sh_prefix << 8) | (unsigned)d;
        }
        __syncthreads();
    }
    const unsigned uT = sh_prefix;
    const int      rr = sh_krem;

    // Count equals per blocked chunk [t*16, t*16+16); exclusive scan via shuffles.
    int cnteq = 0;
    {
        int base = t * 16;
        #pragma unroll
        for (int i = 0; i < 16; i++)
            if (f2o(s_row[base + i]) == uT) cnteq++;
    }
    int inc = cnteq;
    #pragma unroll
    for (int o = 1; o < 32; o <<= 1) {
        int v = __shfl_up_sync(~0u, inc, o);
        if (lane >= o) inc += v;
    }
    if (lane == 31) redi[wrp] = inc;
    __syncthreads();
    int wpre = 0;
    #pragma unroll
    for (int w = 0; w < 8; w++) if (w < wrp) wpre += redi[w];
    const int eqExcl = wpre + inc - cnteq;

    // Build (index, weight) list; ballot-compacted (order irrelevant).
    {
        int base = t * 16;
        int local = 0;
        #pragma unroll
        for (int i = 0; i < 16; i++) {
            float s = s_row[base + i];
            unsigned u = f2o(s);
            bool sel = false;
            if (u > uT) sel = true;
            else if (u == uT) { if (eqExcl + local < rr) sel = true; local++; }
            unsigned m = __ballot_sync(0xffffffffu, sel);
            if (m) {
                int ldr = __ffs(m) - 1;
                int wbase = 0;
                if (lane == ldr) wbase = atomicAdd(&sh_cnt, __popc(m));
                wbase = __shfl_sync(0xffffffffu, wbase, ldr);
                if (sel) {
                    int pos = wbase + __popc(m & ((1u << lane) - 1u));
                    mlist[pos] = base + i;
                    wlist[pos] = __expf(s - smax);
                }
            }
        }
    }
    __syncthreads();
    const int cnt = sh_cnt;           // == KKEEP

    // Z = sum of selected weights (shuffle reduction)
    float z = 0.f;
    for (int i = t; i < cnt; i += 256) z += wlist[i];
    #pragma unroll
    for (int o = 16; o > 0; o >>= 1) z += __shfl_xor_sync(~0u, z, o);
    if (lane == 0) redf[wrp] = z;
    __syncthreads();
    float ztot = redf[0];
    #pragma unroll
    for (int w = 1; w < 8; w++) ztot += redf[w];
    const float invZ = 1.0f / ztot;
    __syncthreads();   // s_row reuse below

    // Sparse AV: thread (q, c4): channel group c4 (4 channels, 8B), quarter q.
    const uint2* V2 = reinterpret_cast<const uint2*>(g_vh + (size_t)b*NN*(CC/2));
    const int c4 = t & 63;
    const int q  = t >> 6;
    float ax = 0.f, ay = 0.f, az = 0.f, aw = 0.f;
    int i = q;
    for (; i + 12 < cnt; i += 16) {
        float w0 = wlist[i],    w1 = wlist[i+4];
        float w2 = wlist[i+8],  w3 = wlist[i+12];
        int   r0 = mlist[i],    r1 = mlist[i+4];
        int   r2 = mlist[i+8],  r3 = mlist[i+12];
        uint2 u0 = V2[(size_t)r0*64 + c4];
        uint2 u1 = V2[(size_t)r1*64 + c4];
        uint2 u2 = V2[(size_t)r2*64 + c4];
        uint2 u3 = V2[(size_t)r3*64 + c4];
        float2 p;
        p = u2f2(u0.x); ax += w0*p.x; ay += w0*p.y;
        p = u2f2(u0.y); az += w0*p.x; aw += w0*p.y;
        p = u2f2(u1.x); ax += w1*p.x; ay += w1*p.y;
        p = u2f2(u1.y); az += w1*p.x; aw += w1*p.y;
        p = u2f2(u2.x); ax += w2*p.x; ay += w2*p.y;
        p = u2f2(u2.y); az += w2*p.x; aw += w2*p.y;
        p = u2f2(u3.x); ax += w3*p.x; ay += w3*p.y;
        p = u2f2(u3.y); az += w3*p.x; aw += w3*p.y;
    }
    for (; i < cnt; i += 4) {
        float w = wlist[i];
        uint2 u = V2[(size_t)mlist[i]*64 + c4];
        float2 p;
        p = u2f2(u.x); ax += w*p.x; ay += w*p.y;
        p = u2f2(u.y); az += w*p.x; aw += w*p.y;
    }

    // Combine quarters 1..3 into quarter 0 via smem; write out[b][c][n].
    float4* comb = (float4*)s_row;
    if (q > 0) comb[(q-1)*64 + c4] = make_float4(ax, ay, az, aw);
    __syncthreads();
    if (q == 0) {
        #pragma unroll
        for (int j = 0; j < 3; j++) {
            float4 v = comb[j*64 + c4];
            ax += v.x; ay += v.y; az += v.z; aw += v.w;
        }
        size_t obase = ((size_t)b*CC + 4*c4)*NN + n;
        out[obase]        = ax * invZ;
        out[obase + NN]   = ay * invZ;
        out[obase + 2*NN] = az * invZ;
        out[obase + 3*NN] = aw * invZ;
    }
}

// ---------------------------------------------------------------------------
extern "C" void kernel_launch(void* const* d_in, const int* in_sizes, int n_in,
                              void* d_out, int out_size)
{
    const float* x  = (const float*)d_in[0];
    const float* Wq = (const float*)d_in[1];
    const float* bq = (const float*)d_in[2];
    const float* Wk = (const float*)d_in[3];
    const float* bk = (const float*)d_in[4];
    const float* Wv = (const float*)d_in[5];
    const float* bv = (const float*)d_in[6];
    float* out = (float*)d_out;

    cudaFuncSetAttribute(scores_mma_kernel,
                         cudaFuncAttributeMaxDynamicSharedMemorySize, SC_SMEM_BYTES);

    proj_kernel      <<<dim3(NN/64,  CC/64, BB*3), 256>>>(x, Wq, bq, Wk, bk, Wv, bv);
    scores_mma_kernel<<<dim3(NN/128, NN/128, BB),  256, SC_SMEM_BYTES>>>();
    topk_av_kernel   <<<dim3(NN, BB), 256>>>(out);
}